// round 14
// baseline (speedup 1.0000x reference)
#include <cuda_runtime.h>
#include <cuda_bf16.h>
#include <cstdint>

// ChamferDistance, symmetric dense: each unique pair (x_n, y_m) computed ONCE
// (full d^2 via packed f32x2 FMA with x^2+y^2 folded in), feeding BOTH the
// per-x row-min and the per-y col-min (redux.sync + lane0 smem atomicMin).
// Halves the FFMA2 stream vs two-direction dense.

#define BATCH    16
#define NPTS     4096
#define THREADS  128
#define QPT      4                        // x-queries per thread
#define QBLK     (THREADS * QPT)          // 512 x per block
#define QTILES   (NPTS / QBLK)            // 8 x-tiles
#define SPLITS   16                       // y slabs
#define RTILE    (NPTS / SPLITS)          // 256 y per block
#define RPAIRS   (RTILE / 2)              // 128 packed pairs
#define TOTX     (BATCH * NPTS)           // 65536 per side
#define R1BLOCKS 256
#define FINF     __int_as_float(0x7f800000)
#define IINF     0x7f800000

__device__ float g_row[SPLITS][TOTX];     // min_m in slab of d^2, per x  (4 MB)
__device__ float g_col[QTILES][TOTX];     // min_n in tile of d^2, per y  (2 MB)
__device__ float g_bsum[R1BLOCKS];

// ---------- packed f32x2 helpers ----------
__device__ __forceinline__ unsigned long long ffma2(unsigned long long a,
                                                    unsigned long long b,
                                                    unsigned long long c) {
    unsigned long long d;
    asm("fma.rn.f32x2 %0, %1, %2, %3;" : "=l"(d) : "l"(a), "l"(b), "l"(c));
    return d;
}
__device__ __forceinline__ unsigned long long fadd2(unsigned long long a,
                                                    unsigned long long b) {
    unsigned long long d;
    asm("add.rn.f32x2 %0, %1, %2;" : "=l"(d) : "l"(a), "l"(b));
    return d;
}
__device__ __forceinline__ unsigned long long pack2(float lo, float hi) {
    unsigned long long d;
    asm("mov.b64 %0, {%1, %2};" : "=l"(d) : "r"(__float_as_uint(lo)), "r"(__float_as_uint(hi)));
    return d;
}
__device__ __forceinline__ void unpack2(unsigned long long v, float& lo, float& hi) {
    unsigned int l, h;
    asm("mov.b64 {%0, %1}, %2;" : "=r"(l), "=r"(h) : "l"(v));
    lo = __uint_as_float(l);
    hi = __uint_as_float(h);
}
__device__ __forceinline__ unsigned redux_min_u32(unsigned v) {
    unsigned d;
    asm("redux.sync.min.u32 %0, %1, 0xffffffff;" : "=r"(d) : "r"(v));
    return d;
}

// ---------------- main: symmetric dense tile ----------------------------------
__global__ __launch_bounds__(THREADS, 6)
void chamfer_main_kernel(const float* __restrict__ x,
                         const float* __restrict__ y) {
    __shared__ float4 shA[RPAIRS];   // (-2x0,-2x1,-2y0,-2y1)  (of y-refs)
    __shared__ float4 shB[RPAIRS];   // (-2z0,-2z1, n0,  n1)
    __shared__ int    scol[RTILE];   // col-min bits per y-ref

    const int qt = blockIdx.x >> 4;           // x tile [0,8)
    const int s  = blockIdx.x & 15;           // y slab [0,16)
    const int b  = blockIdx.y;
    const int tid = threadIdx.x;
    const int lane = tid & 31;

    // Load + transform y slab (1 pair per thread).
    {
        const float* rp = y + ((size_t)b * NPTS + s * RTILE + 2 * tid) * 3;
        float a0 = rp[0], a1 = rp[1], a2 = rp[2];
        float b0 = rp[3], b1 = rp[4], b2 = rp[5];
        float na = fmaf(a0, a0, fmaf(a1, a1, a2 * a2));
        float nb = fmaf(b0, b0, fmaf(b1, b1, b2 * b2));
        shA[tid] = make_float4(-2.0f * a0, -2.0f * b0, -2.0f * a1, -2.0f * b1);
        shB[tid] = make_float4(-2.0f * a2, -2.0f * b2, na, nb);
        scol[tid] = IINF;
        scol[tid + THREADS] = IINF;
    }

    // x-query registers (QPT=4).
    unsigned long long qx2[QPT], qy2[QPT], qz2[QPT], q22[QPT];
    #pragma unroll
    for (int k = 0; k < QPT; k++) {
        int qi = qt * QBLK + k * THREADS + tid;
        const float* qp = x + ((size_t)b * NPTS + qi) * 3;
        float a = qp[0], c = qp[1], d = qp[2];
        qx2[k] = pack2(a, a);
        qy2[k] = pack2(c, c);
        qz2[k] = pack2(d, d);
        float q2 = fmaf(a, a, fmaf(c, c, d * d));
        q22[k] = pack2(q2, q2);
    }

    __syncthreads();

    float mlo[QPT], mhi[QPT];
    #pragma unroll
    for (int k = 0; k < QPT; k++) { mlo[k] = FINF; mhi[k] = FINF; }

    const ulonglong2* __restrict__ A64 = reinterpret_cast<const ulonglong2*>(shA);
    const ulonglong2* __restrict__ B64 = reinterpret_cast<const ulonglong2*>(shB);

    #pragma unroll 4
    for (int j = 0; j < RPAIRS; j++) {
        ulonglong2 va = A64[j];   // .x = xpair, .y = ypair
        ulonglong2 vb = B64[j];   // .x = zpair, .y = y2pair
        float tl[QPT], th[QPT];
        #pragma unroll
        for (int k = 0; k < QPT; k++) {
            unsigned long long c0 = fadd2(vb.y, q22[k]);   // x^2 + y^2 (packed)
            unsigned long long t =
                ffma2(qx2[k], va.x, ffma2(qy2[k], va.y, ffma2(qz2[k], vb.x, c0)));
            unpack2(t, tl[k], th[k]);                      // full d^2 (>= 0)
            mlo[k] = fminf(mlo[k], tl[k]);                 // row mins
            mhi[k] = fminf(mhi[k], th[k]);
        }
        // Col mins: k-reduce then warp-reduce (nonneg floats as u32).
        float cl = fminf(fminf(tl[0], tl[1]), fminf(tl[2], tl[3]));
        float ch = fminf(fminf(th[0], th[1]), fminf(th[2], th[3]));
        unsigned rl = redux_min_u32(__float_as_uint(cl));
        unsigned rh = redux_min_u32(__float_as_uint(ch));
        if (lane == 0) {
            atomicMin(&scol[2 * j],     (int)rl);
            atomicMin(&scol[2 * j + 1], (int)rh);
        }
    }

    // Row partials (full d^2, nothing to add).
    #pragma unroll
    for (int k = 0; k < QPT; k++) {
        int qi = qt * QBLK + k * THREADS + tid;
        g_row[s][(size_t)b * NPTS + qi] = fminf(mlo[k], mhi[k]);
    }

    __syncthreads();
    // Col partials.
    g_col[qt][(size_t)b * NPTS + s * RTILE + tid]           = __int_as_float(scol[tid]);
    g_col[qt][(size_t)b * NPTS + s * RTILE + tid + THREADS] = __int_as_float(scol[tid + THREADS]);
}

// ---------------- stage 2: min over slabs/tiles + block sums ------------------
__global__ __launch_bounds__(256)
void chamfer_reduce1_kernel() {
    __shared__ float ws[8];
    float s = 0.f;
    for (int i = blockIdx.x * 256 + threadIdx.x; i < TOTX / 4; i += R1BLOCKS * 256) {
        float4 m = ((const float4*)&g_row[0][0])[i];
        #pragma unroll
        for (int p = 1; p < SPLITS; p++) {
            float4 v = ((const float4*)&g_row[p][0])[i];
            m.x = fminf(m.x, v.x); m.y = fminf(m.y, v.y);
            m.z = fminf(m.z, v.z); m.w = fminf(m.w, v.w);
        }
        s += (m.x + m.y) + (m.z + m.w);
        float4 c = ((const float4*)&g_col[0][0])[i];
        #pragma unroll
        for (int p = 1; p < QTILES; p++) {
            float4 v = ((const float4*)&g_col[p][0])[i];
            c.x = fminf(c.x, v.x); c.y = fminf(c.y, v.y);
            c.z = fminf(c.z, v.z); c.w = fminf(c.w, v.w);
        }
        s += (c.x + c.y) + (c.z + c.w);
    }
    #pragma unroll
    for (int o = 16; o; o >>= 1) s += __shfl_xor_sync(0xFFFFFFFFu, s, o);
    int lane = threadIdx.x & 31, wid = threadIdx.x >> 5;
    if (lane == 0) ws[wid] = s;
    __syncthreads();
    if (threadIdx.x == 0) {
        float v = 0.f;
        #pragma unroll
        for (int i = 0; i < 8; i++) v += ws[i];
        g_bsum[blockIdx.x] = v;
    }
}

// ---------------- stage 3: final sum ------------------------------------------
__global__ __launch_bounds__(256)
void chamfer_reduce2_kernel(float* __restrict__ out) {
    __shared__ float ws[8];
    float s = (threadIdx.x < R1BLOCKS) ? g_bsum[threadIdx.x] : 0.f;
    #pragma unroll
    for (int o = 16; o; o >>= 1) s += __shfl_xor_sync(0xFFFFFFFFu, s, o);
    int lane = threadIdx.x & 31, wid = threadIdx.x >> 5;
    if (lane == 0) ws[wid] = s;
    __syncthreads();
    if (threadIdx.x == 0) {
        float v = 0.f;
        #pragma unroll
        for (int i = 0; i < 8; i++) v += ws[i];
        out[0] = v * (1.0f / ((float)BATCH * (float)NPTS));
    }
}

extern "C" void kernel_launch(void* const* d_in, const int* in_sizes, int n_in,
                              void* d_out, int out_size) {
    const float* x = (const float*)d_in[0];
    const float* y = (const float*)d_in[1];
    float* out = (float*)d_out;

    dim3 grid(QTILES * SPLITS, BATCH);   // 128 x 16 = 2048 blocks
    chamfer_main_kernel<<<grid, THREADS>>>(x, y);

    chamfer_reduce1_kernel<<<R1BLOCKS, 256>>>();
    chamfer_reduce2_kernel<<<1, 256>>>(out);
}

// round 15
// speedup vs baseline: 2.0121x; 2.0121x over previous
#include <cuda_runtime.h>
#include <cuda_bf16.h>
#include <cstdint>

// ChamferDistance, symmetric dense: each unique (x_n, y_m) pair computed ONCE
// as full d^2 (packed f32x2 FMA, x^2+y^2 folded), feeding both row-min (x, in
// registers) and col-min (y, via lane-staggered warp-private smem RMW --
// no atomics, no redux, no shuffles in the hot loop).

#define BATCH    16
#define NPTS     4096
#define THREADS  128
#define NWARP    (THREADS / 32)
#define QPT      4                        // x-queries per thread
#define QBLK     (THREADS * QPT)          // 512 x per block
#define QTILES   (NPTS / QBLK)            // 8 x-tiles
#define SPLITS   16                       // y slabs
#define RTILE    (NPTS / SPLITS)          // 256 y per block
#define RPAIRS   (RTILE / 2)              // 128 packed pairs
#define TOTX     (BATCH * NPTS)           // 65536 per side
#define R1BLOCKS 256
#define FINF     __int_as_float(0x7f800000)

__device__ float g_row[SPLITS][TOTX];     // per-slab row partial mins (4 MB)
__device__ float g_col[QTILES][TOTX];     // per-tile col partial mins (2 MB)
__device__ float g_bsum[R1BLOCKS];

// ---------- packed f32x2 helpers ----------
__device__ __forceinline__ unsigned long long ffma2(unsigned long long a,
                                                    unsigned long long b,
                                                    unsigned long long c) {
    unsigned long long d;
    asm("fma.rn.f32x2 %0, %1, %2, %3;" : "=l"(d) : "l"(a), "l"(b), "l"(c));
    return d;
}
__device__ __forceinline__ unsigned long long fadd2(unsigned long long a,
                                                    unsigned long long b) {
    unsigned long long d;
    asm("add.rn.f32x2 %0, %1, %2;" : "=l"(d) : "l"(a), "l"(b));
    return d;
}
__device__ __forceinline__ unsigned long long pack2(float lo, float hi) {
    unsigned long long d;
    asm("mov.b64 %0, {%1, %2};" : "=l"(d) : "r"(__float_as_uint(lo)), "r"(__float_as_uint(hi)));
    return d;
}
__device__ __forceinline__ void unpack2(unsigned long long v, float& lo, float& hi) {
    unsigned int l, h;
    asm("mov.b64 {%0, %1}, %2;" : "=r"(l), "=r"(h) : "l"(v));
    lo = __uint_as_float(l);
    hi = __uint_as_float(h);
}
// Volatile shared v2 ld/st: keeps cross-step RMW ordering (warp-synchronous).
__device__ __forceinline__ float2 lds_v2v(unsigned sa) {
    float2 v;
    asm volatile("ld.volatile.shared.v2.f32 {%0,%1}, [%2];"
                 : "=f"(v.x), "=f"(v.y) : "r"(sa) : "memory");
    return v;
}
__device__ __forceinline__ void sts_v2v(unsigned sa, float2 v) {
    asm volatile("st.volatile.shared.v2.f32 [%0], {%1,%2};"
                 :: "r"(sa), "f"(v.x), "f"(v.y) : "memory");
}

// ---------------- main: symmetric dense tile ----------------------------------
__global__ __launch_bounds__(THREADS, 5)
void chamfer_main_kernel(const float* __restrict__ x,
                         const float* __restrict__ y) {
    __shared__ float4 shA[RPAIRS];            // (-2x0,-2x1,-2y0,-2y1) of y-refs
    __shared__ float4 shB[RPAIRS];            // (-2z0,-2z1, n0,  n1)
    __shared__ float2 scol[NWARP][RPAIRS];    // warp-private col mins (4 KB)

    const int qt  = blockIdx.x >> 4;          // x tile [0,8)
    const int s   = blockIdx.x & 15;          // y slab [0,16)
    const int b   = blockIdx.y;
    const int tid = threadIdx.x;
    const int lane = tid & 31;
    const int wid  = tid >> 5;

    // Load + transform y slab (1 pair per thread).
    {
        const float* rp = y + ((size_t)b * NPTS + s * RTILE + 2 * tid) * 3;
        float a0 = rp[0], a1 = rp[1], a2 = rp[2];
        float b0 = rp[3], b1 = rp[4], b2 = rp[5];
        float na = fmaf(a0, a0, fmaf(a1, a1, a2 * a2));
        float nb = fmaf(b0, b0, fmaf(b1, b1, b2 * b2));
        shA[tid] = make_float4(-2.0f * a0, -2.0f * b0, -2.0f * a1, -2.0f * b1);
        shB[tid] = make_float4(-2.0f * a2, -2.0f * b2, na, nb);
    }
    // Init warp-private col arrays.
    {
        float2* flat = &scol[0][0];
        #pragma unroll
        for (int i = tid; i < NWARP * RPAIRS; i += THREADS)
            flat[i] = make_float2(FINF, FINF);
    }

    // x-query registers (QPT=4), with ||x||^2 packed for the d^2 fold.
    unsigned long long qx2[QPT], qy2[QPT], qz2[QPT], q22[QPT];
    #pragma unroll
    for (int k = 0; k < QPT; k++) {
        int qi = qt * QBLK + k * THREADS + tid;
        const float* qp = x + ((size_t)b * NPTS + qi) * 3;
        float a = qp[0], c = qp[1], d = qp[2];
        qx2[k] = pack2(a, a);
        qy2[k] = pack2(c, c);
        qz2[k] = pack2(d, d);
        float q2 = fmaf(a, a, fmaf(c, c, d * d));
        q22[k] = pack2(q2, q2);
    }

    __syncthreads();

    float mlo[QPT], mhi[QPT];
    #pragma unroll
    for (int k = 0; k < QPT; k++) { mlo[k] = FINF; mhi[k] = FINF; }

    const ulonglong2* __restrict__ A64 = reinterpret_cast<const ulonglong2*>(shA);
    const ulonglong2* __restrict__ B64 = reinterpret_cast<const ulonglong2*>(shB);
    const unsigned scol_base =
        (unsigned)__cvta_generic_to_shared(&scol[wid][0]);

    #pragma unroll 4
    for (int j = 0; j < RPAIRS; j++) {
        const int p = (lane + j) & (RPAIRS - 1);   // lanes own distinct pairs
        ulonglong2 va = A64[p];   // .x = xpair, .y = ypair
        ulonglong2 vb = B64[p];   // .x = zpair, .y = y2pair
        float tl[QPT], th[QPT];
        #pragma unroll
        for (int k = 0; k < QPT; k++) {
            unsigned long long c0 = fadd2(vb.y, q22[k]);   // x^2+y^2 (packed)
            unsigned long long t =
                ffma2(qx2[k], va.x, ffma2(qy2[k], va.y, ffma2(qz2[k], vb.x, c0)));
            unpack2(t, tl[k], th[k]);                      // full d^2
            mlo[k] = fminf(mlo[k], tl[k]);                 // row mins (regs)
            mhi[k] = fminf(mhi[k], th[k]);
        }
        // Col mins for this lane's private pair: k-reduce + smem RMW.
        float cl = fminf(fminf(tl[0], tl[1]), fminf(tl[2], tl[3]));
        float ch = fminf(fminf(th[0], th[1]), fminf(th[2], th[3]));
        unsigned sa = scol_base + (unsigned)p * 8u;
        float2 cur = lds_v2v(sa);
        cur.x = fminf(cur.x, cl);
        cur.y = fminf(cur.y, ch);
        sts_v2v(sa, cur);
    }

    // Row partials.
    #pragma unroll
    for (int k = 0; k < QPT; k++) {
        int qi = qt * QBLK + k * THREADS + tid;
        g_row[s][(size_t)b * NPTS + qi] = fminf(mlo[k], mhi[k]);
    }

    __syncthreads();
    // Combine warp-private col arrays, write col partials (1 pair per thread).
    {
        float2 c0 = scol[0][tid];
        float2 c1 = scol[1][tid];
        float2 c2 = scol[2][tid];
        float2 c3 = scol[3][tid];
        float2 m;
        m.x = fminf(fminf(c0.x, c1.x), fminf(c2.x, c3.x));
        m.y = fminf(fminf(c0.y, c1.y), fminf(c2.y, c3.y));
        float2* dst = (float2*)&g_col[qt][(size_t)b * NPTS + s * RTILE];
        dst[tid] = m;
    }
}

// ---------------- stage 2: min over slabs/tiles + block sums ------------------
__global__ __launch_bounds__(256)
void chamfer_reduce1_kernel() {
    __shared__ float ws[8];
    float s = 0.f;
    for (int i = blockIdx.x * 256 + threadIdx.x; i < TOTX / 4; i += R1BLOCKS * 256) {
        float4 m = ((const float4*)&g_row[0][0])[i];
        #pragma unroll
        for (int p = 1; p < SPLITS; p++) {
            float4 v = ((const float4*)&g_row[p][0])[i];
            m.x = fminf(m.x, v.x); m.y = fminf(m.y, v.y);
            m.z = fminf(m.z, v.z); m.w = fminf(m.w, v.w);
        }
        s += (m.x + m.y) + (m.z + m.w);
        float4 c = ((const float4*)&g_col[0][0])[i];
        #pragma unroll
        for (int p = 1; p < QTILES; p++) {
            float4 v = ((const float4*)&g_col[p][0])[i];
            c.x = fminf(c.x, v.x); c.y = fminf(c.y, v.y);
            c.z = fminf(c.z, v.z); c.w = fminf(c.w, v.w);
        }
        s += (c.x + c.y) + (c.z + c.w);
    }
    #pragma unroll
    for (int o = 16; o; o >>= 1) s += __shfl_xor_sync(0xFFFFFFFFu, s, o);
    int lane = threadIdx.x & 31, wid = threadIdx.x >> 5;
    if (lane == 0) ws[wid] = s;
    __syncthreads();
    if (threadIdx.x == 0) {
        float v = 0.f;
        #pragma unroll
        for (int i = 0; i < 8; i++) v += ws[i];
        g_bsum[blockIdx.x] = v;
    }
}

// ---------------- stage 3: final sum ------------------------------------------
__global__ __launch_bounds__(256)
void chamfer_reduce2_kernel(float* __restrict__ out) {
    __shared__ float ws[8];
    float s = (threadIdx.x < R1BLOCKS) ? g_bsum[threadIdx.x] : 0.f;
    #pragma unroll
    for (int o = 16; o; o >>= 1) s += __shfl_xor_sync(0xFFFFFFFFu, s, o);
    int lane = threadIdx.x & 31, wid = threadIdx.x >> 5;
    if (lane == 0) ws[wid] = s;
    __syncthreads();
    if (threadIdx.x == 0) {
        float v = 0.f;
        #pragma unroll
        for (int i = 0; i < 8; i++) v += ws[i];
        out[0] = v * (1.0f / ((float)BATCH * (float)NPTS));
    }
}

extern "C" void kernel_launch(void* const* d_in, const int* in_sizes, int n_in,
                              void* d_out, int out_size) {
    const float* x = (const float*)d_in[0];
    const float* y = (const float*)d_in[1];
    float* out = (float*)d_out;

    dim3 grid(QTILES * SPLITS, BATCH);   // 128 x 16 = 2048 blocks
    chamfer_main_kernel<<<grid, THREADS>>>(x, y);

    chamfer_reduce1_kernel<<<R1BLOCKS, 256>>>();
    chamfer_reduce2_kernel<<<1, 256>>>(out);
}

// round 16
// speedup vs baseline: 2.0610x; 1.0243x over previous
#include <cuda_runtime.h>
#include <cuda_bf16.h>
#include <cstdint>

// ChamferDistance, symmetric dense: each unique (x_n, y_m) pair computed ONCE
// as full d^2 (packed f32x2 FMA, x^2+y^2 folded), feeding both row-min (x, in
// registers) and col-min (y, lane-staggered warp-private smem RMW).
// QPT=8 dilutes smem+alu per fma: loop is fma-bound at the packed-FMA floor.

#define BATCH    16
#define NPTS     4096
#define THREADS  128
#define NWARP    (THREADS / 32)
#define QPT      8                        // x-queries per thread
#define QBLK     (THREADS * QPT)          // 1024 x per block
#define QTILES   (NPTS / QBLK)            // 4 x-tiles
#define SPLITS   32                       // y slabs
#define RTILE    (NPTS / SPLITS)          // 128 y per block
#define RPAIRS   (RTILE / 2)              // 64 packed pairs
#define TOTX     (BATCH * NPTS)           // 65536 per side
#define R1BLOCKS 64
#define FINF     __int_as_float(0x7f800000)

__device__ float g_row[SPLITS][TOTX];     // per-slab row partial mins (8 MB)
__device__ float g_col[QTILES][TOTX];     // per-tile col partial mins (1 MB)
__device__ float g_bsum[R1BLOCKS];

// ---------- packed f32x2 helpers ----------
__device__ __forceinline__ unsigned long long ffma2(unsigned long long a,
                                                    unsigned long long b,
                                                    unsigned long long c) {
    unsigned long long d;
    asm("fma.rn.f32x2 %0, %1, %2, %3;" : "=l"(d) : "l"(a), "l"(b), "l"(c));
    return d;
}
__device__ __forceinline__ unsigned long long fadd2(unsigned long long a,
                                                    unsigned long long b) {
    unsigned long long d;
    asm("add.rn.f32x2 %0, %1, %2;" : "=l"(d) : "l"(a), "l"(b));
    return d;
}
__device__ __forceinline__ unsigned long long pack2(float lo, float hi) {
    unsigned long long d;
    asm("mov.b64 %0, {%1, %2};" : "=l"(d) : "r"(__float_as_uint(lo)), "r"(__float_as_uint(hi)));
    return d;
}
__device__ __forceinline__ void unpack2(unsigned long long v, float& lo, float& hi) {
    unsigned int l, h;
    asm("mov.b64 {%0, %1}, %2;" : "=r"(l), "=r"(h) : "l"(v));
    lo = __uint_as_float(l);
    hi = __uint_as_float(h);
}
// Volatile shared v2 ld/st for the warp-synchronous cross-step RMW.
__device__ __forceinline__ float2 lds_v2v(unsigned sa) {
    float2 v;
    asm volatile("ld.volatile.shared.v2.f32 {%0,%1}, [%2];"
                 : "=f"(v.x), "=f"(v.y) : "r"(sa) : "memory");
    return v;
}
__device__ __forceinline__ void sts_v2v(unsigned sa, float2 v) {
    asm volatile("st.volatile.shared.v2.f32 [%0], {%1,%2};"
                 :: "r"(sa), "f"(v.x), "f"(v.y) : "memory");
}

// ---------------- main: symmetric dense tile ----------------------------------
__global__ __launch_bounds__(THREADS, 4)
void chamfer_main_kernel(const float* __restrict__ x,
                         const float* __restrict__ y) {
    __shared__ float4 shA[RPAIRS];            // (-2x0,-2x1,-2y0,-2y1) of y-refs
    __shared__ float4 shB[RPAIRS];            // (-2z0,-2z1, n0,  n1)
    __shared__ float2 scol[NWARP][RPAIRS];    // warp-private col mins (2 KB)

    const int qt  = blockIdx.x >> 5;          // x tile [0,4)
    const int s   = blockIdx.x & 31;          // y slab [0,32)
    const int b   = blockIdx.y;
    const int tid = threadIdx.x;
    const int lane = tid & 31;
    const int wid  = tid >> 5;

    // Load + transform y slab (64 pairs; threads 0-63).
    if (tid < RPAIRS) {
        const float* rp = y + ((size_t)b * NPTS + s * RTILE + 2 * tid) * 3;
        float a0 = rp[0], a1 = rp[1], a2 = rp[2];
        float b0 = rp[3], b1 = rp[4], b2 = rp[5];
        float na = fmaf(a0, a0, fmaf(a1, a1, a2 * a2));
        float nb = fmaf(b0, b0, fmaf(b1, b1, b2 * b2));
        shA[tid] = make_float4(-2.0f * a0, -2.0f * b0, -2.0f * a1, -2.0f * b1);
        shB[tid] = make_float4(-2.0f * a2, -2.0f * b2, na, nb);
    }
    // Init warp-private col arrays.
    {
        float2* flat = &scol[0][0];
        #pragma unroll
        for (int i = tid; i < NWARP * RPAIRS; i += THREADS)
            flat[i] = make_float2(FINF, FINF);
    }

    // x-query registers (QPT=8), with ||x||^2 packed for the d^2 fold.
    unsigned long long qx2[QPT], qy2[QPT], qz2[QPT], q22[QPT];
    #pragma unroll
    for (int k = 0; k < QPT; k++) {
        int qi = qt * QBLK + k * THREADS + tid;
        const float* qp = x + ((size_t)b * NPTS + qi) * 3;
        float a = qp[0], c = qp[1], d = qp[2];
        qx2[k] = pack2(a, a);
        qy2[k] = pack2(c, c);
        qz2[k] = pack2(d, d);
        float q2 = fmaf(a, a, fmaf(c, c, d * d));
        q22[k] = pack2(q2, q2);
    }

    __syncthreads();

    float mlo[QPT], mhi[QPT];
    #pragma unroll
    for (int k = 0; k < QPT; k++) { mlo[k] = FINF; mhi[k] = FINF; }

    const ulonglong2* __restrict__ A64 = reinterpret_cast<const ulonglong2*>(shA);
    const ulonglong2* __restrict__ B64 = reinterpret_cast<const ulonglong2*>(shB);
    const unsigned scol_base =
        (unsigned)__cvta_generic_to_shared(&scol[wid][0]);

    #pragma unroll 2
    for (int j = 0; j < RPAIRS; j++) {
        const int p = (lane + j) & (RPAIRS - 1);   // lanes own distinct pairs
        ulonglong2 va = A64[p];   // .x = xpair, .y = ypair
        ulonglong2 vb = B64[p];   // .x = zpair, .y = y2pair
        float tl[QPT], th[QPT];
        #pragma unroll
        for (int k = 0; k < QPT; k++) {
            unsigned long long c0 = fadd2(vb.y, q22[k]);   // x^2+y^2 (packed)
            unsigned long long t =
                ffma2(qx2[k], va.x, ffma2(qy2[k], va.y, ffma2(qz2[k], vb.x, c0)));
            unpack2(t, tl[k], th[k]);                      // full d^2
            mlo[k] = fminf(mlo[k], tl[k]);                 // row mins (regs)
            mhi[k] = fminf(mhi[k], th[k]);
        }
        // Col mins for this lane's private pair: k-tree-reduce + smem RMW.
        float cl = fminf(fminf(fminf(tl[0], tl[1]), fminf(tl[2], tl[3])),
                         fminf(fminf(tl[4], tl[5]), fminf(tl[6], tl[7])));
        float ch = fminf(fminf(fminf(th[0], th[1]), fminf(th[2], th[3])),
                         fminf(fminf(th[4], th[5]), fminf(th[6], th[7])));
        unsigned sa = scol_base + (unsigned)p * 8u;
        float2 cur = lds_v2v(sa);
        cur.x = fminf(cur.x, cl);
        cur.y = fminf(cur.y, ch);
        sts_v2v(sa, cur);
    }

    // Row partials.
    #pragma unroll
    for (int k = 0; k < QPT; k++) {
        int qi = qt * QBLK + k * THREADS + tid;
        g_row[s][(size_t)b * NPTS + qi] = fminf(mlo[k], mhi[k]);
    }

    __syncthreads();
    // Combine warp-private col arrays, write col partials (threads 0-63).
    if (tid < RPAIRS) {
        float2 c0 = scol[0][tid];
        float2 c1 = scol[1][tid];
        float2 c2 = scol[2][tid];
        float2 c3 = scol[3][tid];
        float2 m;
        m.x = fminf(fminf(c0.x, c1.x), fminf(c2.x, c3.x));
        m.y = fminf(fminf(c0.y, c1.y), fminf(c2.y, c3.y));
        float2* dst = (float2*)&g_col[qt][(size_t)b * NPTS + s * RTILE];
        dst[tid] = m;
    }
}

// ---------------- stage 2: min over slabs/tiles + block sums ------------------
__global__ __launch_bounds__(256)
void chamfer_reduce1_kernel() {
    __shared__ float ws[8];
    float s = 0.f;
    for (int i = blockIdx.x * 256 + threadIdx.x; i < TOTX / 4; i += R1BLOCKS * 256) {
        float4 m = ((const float4*)&g_row[0][0])[i];
        #pragma unroll
        for (int p = 1; p < SPLITS; p++) {
            float4 v = ((const float4*)&g_row[p][0])[i];
            m.x = fminf(m.x, v.x); m.y = fminf(m.y, v.y);
            m.z = fminf(m.z, v.z); m.w = fminf(m.w, v.w);
        }
        s += (m.x + m.y) + (m.z + m.w);
        float4 c = ((const float4*)&g_col[0][0])[i];
        #pragma unroll
        for (int p = 1; p < QTILES; p++) {
            float4 v = ((const float4*)&g_col[p][0])[i];
            c.x = fminf(c.x, v.x); c.y = fminf(c.y, v.y);
            c.z = fminf(c.z, v.z); c.w = fminf(c.w, v.w);
        }
        s += (c.x + c.y) + (c.z + c.w);
    }
    #pragma unroll
    for (int o = 16; o; o >>= 1) s += __shfl_xor_sync(0xFFFFFFFFu, s, o);
    int lane = threadIdx.x & 31, wid = threadIdx.x >> 5;
    if (lane == 0) ws[wid] = s;
    __syncthreads();
    if (threadIdx.x == 0) {
        float v = 0.f;
        #pragma unroll
        for (int i = 0; i < 8; i++) v += ws[i];
        g_bsum[blockIdx.x] = v;
    }
}

// ---------------- stage 3: final sum ------------------------------------------
__global__ __launch_bounds__(256)
void chamfer_reduce2_kernel(float* __restrict__ out) {
    __shared__ float ws[8];
    float s = (threadIdx.x < R1BLOCKS) ? g_bsum[threadIdx.x] : 0.f;
    #pragma unroll
    for (int o = 16; o; o >>= 1) s += __shfl_xor_sync(0xFFFFFFFFu, s, o);
    int lane = threadIdx.x & 31, wid = threadIdx.x >> 5;
    if (lane == 0) ws[wid] = s;
    __syncthreads();
    if (threadIdx.x == 0) {
        float v = 0.f;
        #pragma unroll
        for (int i = 0; i < 8; i++) v += ws[i];
        out[0] = v * (1.0f / ((float)BATCH * (float)NPTS));
    }
}

extern "C" void kernel_launch(void* const* d_in, const int* in_sizes, int n_in,
                              void* d_out, int out_size) {
    const float* x = (const float*)d_in[0];
    const float* y = (const float*)d_in[1];
    float* out = (float*)d_out;

    dim3 grid(QTILES * SPLITS, BATCH);   // 128 x 16 = 2048 blocks
    chamfer_main_kernel<<<grid, THREADS>>>(x, y);

    chamfer_reduce1_kernel<<<R1BLOCKS, 256>>>();
    chamfer_reduce2_kernel<<<1, 256>>>(out);
}